// round 17
// baseline (speedup 1.0000x reference)
#include <cuda_runtime.h>
#include <cuda_fp16.h>
#include <math.h>

// Problem constants
#define BB   2
#define HH   16
#define SS   2048
#define DD   1024
#define DK   64
#define BHN  (BB*HH)      // 32
#define KEEP 1843         // int(2048*0.9)

typedef unsigned int u32;

// ---------------- scratch (device globals; no cudaMalloc allowed) ----------
__device__ float  g_qh[(size_t)BHN * SS * DK];      // [b,h,s,d]
__device__ float  g_kh[(size_t)BHN * SS * DK];
__device__ float  g_vh[(size_t)BHN * SS * DK];
__device__ float  g_probs[(size_t)BHN * SS * SS];   // 512 MiB fp32 scores
__device__ __half g_probsh[(size_t)BHN * SS * SS];  // 256 MiB fp16 probs
__device__ float  g_part[(size_t)BHN * 32 * SS];    // colsum partials
__device__ float  g_mask[BHN * SS];
__device__ __half g_concath[(size_t)BB * SS * DD];  // fp16 concat [b,s,h*64+d]

// ============================================================================
// FFMA fp32 NT GEMM body, double-buffered smem; m0/n0 passed in.
// Accumulation order identical to R1..R13 => bitwise-same results.
// MODE 0: row-major C (ldc); MODE 1: head-scatter [b,h,s,d].
// ============================================================================
template<int MODE>
__device__ __forceinline__ void ffma_tile(
    const float* __restrict__ A, const float* __restrict__ B,
    float* __restrict__ C, const float* __restrict__ bias,
    int K, int lda, int ldb, int ldc, float alpha, int m0, int n0,
    float As[2][8][128], float Bs[2][8][128])
{
    const int tid = threadIdx.x;
    const int tx = tid & 15;
    const int ty = tid >> 4;
    const int lrow = tid >> 1;
    const int lcol = (tid & 1) * 4;

    float acc[8][8];
#pragma unroll
    for (int i = 0; i < 8; i++)
#pragma unroll
        for (int j = 0; j < 8; j++) acc[i][j] = 0.f;

    const float* Aptr = A + (size_t)(m0 + lrow) * lda + lcol;
    const float* Bptr = B + (size_t)(n0 + lrow) * ldb + lcol;

    {
        float4 av = *(const float4*)(Aptr);
        float4 bv = *(const float4*)(Bptr);
        As[0][lcol + 0][lrow] = av.x; As[0][lcol + 1][lrow] = av.y;
        As[0][lcol + 2][lrow] = av.z; As[0][lcol + 3][lrow] = av.w;
        Bs[0][lcol + 0][lrow] = bv.x; Bs[0][lcol + 1][lrow] = bv.y;
        Bs[0][lcol + 2][lrow] = bv.z; Bs[0][lcol + 3][lrow] = bv.w;
    }
    __syncthreads();

    int buf = 0;
    for (int k0 = 8; k0 < K; k0 += 8) {
        float4 av = *(const float4*)(Aptr + k0);
        float4 bv = *(const float4*)(Bptr + k0);
        const int nb = buf ^ 1;
        As[nb][lcol + 0][lrow] = av.x; As[nb][lcol + 1][lrow] = av.y;
        As[nb][lcol + 2][lrow] = av.z; As[nb][lcol + 3][lrow] = av.w;
        Bs[nb][lcol + 0][lrow] = bv.x; Bs[nb][lcol + 1][lrow] = bv.y;
        Bs[nb][lcol + 2][lrow] = bv.z; Bs[nb][lcol + 3][lrow] = bv.w;
#pragma unroll
        for (int kk = 0; kk < 8; kk++) {
            float a[8], b[8];
            *(float4*)(a)     = *(const float4*)&As[buf][kk][ty * 8];
            *(float4*)(a + 4) = *(const float4*)&As[buf][kk][ty * 8 + 4];
            *(float4*)(b)     = *(const float4*)&Bs[buf][kk][tx * 8];
            *(float4*)(b + 4) = *(const float4*)&Bs[buf][kk][tx * 8 + 4];
#pragma unroll
            for (int i = 0; i < 8; i++)
#pragma unroll
                for (int j = 0; j < 8; j++) acc[i][j] += a[i] * b[j];
        }
        __syncthreads();
        buf = nb;
    }
#pragma unroll
    for (int kk = 0; kk < 8; kk++) {
        float a[8], b[8];
        *(float4*)(a)     = *(const float4*)&As[buf][kk][ty * 8];
        *(float4*)(a + 4) = *(const float4*)&As[buf][kk][ty * 8 + 4];
        *(float4*)(b)     = *(const float4*)&Bs[buf][kk][tx * 8];
        *(float4*)(b + 4) = *(const float4*)&Bs[buf][kk][tx * 8 + 4];
#pragma unroll
        for (int i = 0; i < 8; i++)
#pragma unroll
            for (int j = 0; j < 8; j++) acc[i][j] += a[i] * b[j];
    }

    if (MODE == 0) {
#pragma unroll
        for (int i = 0; i < 8; i++) {
            int m = m0 + ty * 8 + i;
            float out[8];
#pragma unroll
            for (int j = 0; j < 8; j++) {
                int n = n0 + tx * 8 + j;
                out[j] = acc[i][j] * alpha + (bias ? bias[n] : 0.f);
            }
            float* crow = C + (size_t)m * ldc + n0 + tx * 8;
            *(float4*)(crow)     = *(float4*)(out);
            *(float4*)(crow + 4) = *(float4*)(out + 4);
        }
    } else {
#pragma unroll
        for (int i = 0; i < 8; i++) {
            int m = m0 + ty * 8 + i;
            int b = m >> 11;
            int s = m & (SS - 1);
#pragma unroll
            for (int j = 0; j < 8; j++) {
                int n = n0 + tx * 8 + j;
                int h = n >> 6;
                int d = n & 63;
                C[(((size_t)(b * HH + h)) * SS + s) * DK + d] =
                    acc[i][j] * alpha + (bias ? bias[n] : 0.f);
            }
        }
    }
}

// ============================================================================
// fp16 mma primitive
// ============================================================================
static __device__ __forceinline__ void mma_f16(float* d, const u32* a, const u32* b) {
    asm volatile(
        "mma.sync.aligned.m16n8k16.row.col.f32.f16.f16.f32 "
        "{%0,%1,%2,%3}, {%4,%5,%6,%7}, {%8,%9}, {%0,%1,%2,%3};"
        : "+f"(d[0]), "+f"(d[1]), "+f"(d[2]), "+f"(d[3])
        : "r"(a[0]), "r"(a[1]), "r"(a[2]), "r"(a[3]), "r"(b[0]), "r"(b[1]));
}

// Scaled 3-way fp16 split: x = h1 + h2/2048 + h3/2048 (h2,h3 pre-scaled)
static __device__ __forceinline__ void split3(float x, __half& h1, __half& h2,
                                              __half& h3)
{
    h1 = __float2half_rn(x);
    float r1 = x - __half2float(h1);
    h2 = __float2half_rn(r1 * 2048.f);
    float r2 = r1 - __half2float(h2) * (1.f / 2048.f);
    h3 = __float2half_rn(r2 * 2048.f);
}

// ============================================================================
// Generic fp16x6 (fp32-grade) NT GEMM tile: C = alpha * A @ B^T (+bias).
// CTA tile 128x64, BK=32, 8 warps 2(m)x4(n), warp tile 64x16 (NFR=2).
// ============================================================================
template<int MODE>
__device__ void f16x6_tile(const float* __restrict__ A,
                           const float* __restrict__ B,
                           float* __restrict__ C,
                           const float* __restrict__ bias,
                           int K, int lda, int ldb, int ldc,
                           float alpha, int m0, int n0, char* smem_raw)
{
    typedef __half (*H40)[40];
    H40 A1 = (H40)(smem_raw);
    H40 A2 = (H40)(smem_raw + 10240);
    H40 A3 = (H40)(smem_raw + 20480);
    H40 B1 = (H40)(smem_raw + 30720);
    H40 B2 = (H40)(smem_raw + 35840);
    H40 B3 = (H40)(smem_raw + 40960);

    const int tid  = threadIdx.x;
    const int wid  = tid >> 5;
    const int lane = tid & 31;
    const int wm   = wid & 1;
    const int wn   = wid >> 1;       // 0..3
    const int qid  = lane >> 2;
    const int rid  = lane & 3;

    float acc0[4][2][4], acc1[4][2][4];
#pragma unroll
    for (int i = 0; i < 4; i++)
#pragma unroll
        for (int j = 0; j < 2; j++)
#pragma unroll
            for (int t = 0; t < 4; t++) { acc0[i][j][t] = 0.f; acc1[i][j][t] = 0.f; }

    const __half2 inv_s2 = __float2half2_rn(1.f / 2048.f);
    const int nc = K >> 5;

    for (int c = 0; c < nc; c++) {
        const int k0 = c << 5;
        float4 va[4], vb[2];
#pragma unroll
        for (int i = 0; i < 4; i++) {
            int idx = tid + i * 256;
            int r = idx >> 3, cc = (idx & 7) << 2;
            va[i] = *(const float4*)(A + (size_t)(m0 + r) * lda + k0 + cc);
        }
#pragma unroll
        for (int i = 0; i < 2; i++) {
            int idx = tid + i * 256;
            int r = idx >> 3, cc = (idx & 7) << 2;
            vb[i] = *(const float4*)(B + (size_t)(n0 + r) * ldb + k0 + cc);
        }
        __syncthreads();
#pragma unroll
        for (int i = 0; i < 4; i++) {
            int idx = tid + i * 256;
            int r = idx >> 3, cc = (idx & 7) << 2;
            float xs[4] = {va[i].x, va[i].y, va[i].z, va[i].w};
#pragma unroll
            for (int t = 0; t < 4; t++)
                split3(xs[t], A1[r][cc + t], A2[r][cc + t], A3[r][cc + t]);
        }
#pragma unroll
        for (int i = 0; i < 2; i++) {
            int idx = tid + i * 256;
            int r = idx >> 3, cc = (idx & 7) << 2;
            float xs[4] = {vb[i].x, vb[i].y, vb[i].z, vb[i].w};
#pragma unroll
            for (int t = 0; t < 4; t++)
                split3(xs[t], B1[r][cc + t], B2[r][cc + t], B3[r][cc + t]);
        }
        __syncthreads();

#pragma unroll
        for (int kk = 0; kk < 32; kk += 16) {
            u32 a1[4][4], a2[4][4], a3[4][4];
#pragma unroll
            for (int mt = 0; mt < 4; mt++) {
                int row = wm * 64 + mt * 16 + qid;
                a1[mt][0] = *(const u32*)&A1[row    ][kk + rid * 2];
                a1[mt][1] = *(const u32*)&A1[row + 8][kk + rid * 2];
                a1[mt][2] = *(const u32*)&A1[row    ][kk + rid * 2 + 8];
                a1[mt][3] = *(const u32*)&A1[row + 8][kk + rid * 2 + 8];
                a2[mt][0] = *(const u32*)&A2[row    ][kk + rid * 2];
                a2[mt][1] = *(const u32*)&A2[row + 8][kk + rid * 2];
                a2[mt][2] = *(const u32*)&A2[row    ][kk + rid * 2 + 8];
                a2[mt][3] = *(const u32*)&A2[row + 8][kk + rid * 2 + 8];
                a3[mt][0] = *(const u32*)&A3[row    ][kk + rid * 2];
                a3[mt][1] = *(const u32*)&A3[row + 8][kk + rid * 2];
                a3[mt][2] = *(const u32*)&A3[row    ][kk + rid * 2 + 8];
                a3[mt][3] = *(const u32*)&A3[row + 8][kk + rid * 2 + 8];
            }
            u32 b1[2][2], b2[2][2], b3[2][2], b2r[2][2];
#pragma unroll
            for (int nt = 0; nt < 2; nt++) {
                int col = wn * 16 + nt * 8 + qid;
                b1[nt][0] = *(const u32*)&B1[col][kk + rid * 2];
                b1[nt][1] = *(const u32*)&B1[col][kk + rid * 2 + 8];
                b2[nt][0] = *(const u32*)&B2[col][kk + rid * 2];
                b2[nt][1] = *(const u32*)&B2[col][kk + rid * 2 + 8];
                b3[nt][0] = *(const u32*)&B3[col][kk + rid * 2];
                b3[nt][1] = *(const u32*)&B3[col][kk + rid * 2 + 8];
                __half2 t0 = __hmul2(*(__half2*)&b2[nt][0], inv_s2);
                __half2 t1 = __hmul2(*(__half2*)&b2[nt][1], inv_s2);
                b2r[nt][0] = *(u32*)&t0;
                b2r[nt][1] = *(u32*)&t1;
            }
#pragma unroll
            for (int mt = 0; mt < 4; mt++)
#pragma unroll
                for (int nt = 0; nt < 2; nt++) {
                    mma_f16(acc0[mt][nt], a1[mt], b1[nt]);
                    mma_f16(acc1[mt][nt], a1[mt], b2[nt]);
                    mma_f16(acc1[mt][nt], a2[mt], b1[nt]);
                    mma_f16(acc1[mt][nt], a1[mt], b3[nt]);
                    mma_f16(acc1[mt][nt], a3[mt], b1[nt]);
                    mma_f16(acc1[mt][nt], a2[mt], b2r[nt]);
                }
        }
        __syncthreads();
    }

    const float S = 1.f / 2048.f;
#pragma unroll
    for (int mt = 0; mt < 4; mt++) {
        int r0 = m0 + wm * 64 + mt * 16 + qid;
        int r1 = r0 + 8;
#pragma unroll
        for (int nt = 0; nt < 2; nt++) {
            int cb = n0 + wn * 16 + nt * 8 + rid * 2;
            float v0 = (acc0[mt][nt][0] + acc1[mt][nt][0] * S) * alpha;
            float v1 = (acc0[mt][nt][1] + acc1[mt][nt][1] * S) * alpha;
            float v2 = (acc0[mt][nt][2] + acc1[mt][nt][2] * S) * alpha;
            float v3 = (acc0[mt][nt][3] + acc1[mt][nt][3] * S) * alpha;
            if (MODE == 0) {
                *(float2*)(C + (size_t)r0 * ldc + cb) = make_float2(v0, v1);
                *(float2*)(C + (size_t)r1 * ldc + cb) = make_float2(v2, v3);
            } else {
                float b0 = bias[cb], b1 = bias[cb + 1];
                v0 += b0; v1 += b1; v2 += b0; v3 += b1;
                int h = cb >> 6, d = cb & 63;
                int b0i = r0 >> 11, s0i = r0 & (SS - 1);
                int b1i = r1 >> 11, s1i = r1 & (SS - 1);
                *(float2*)(C + (((size_t)(b0i * HH + h)) * SS + s0i) * DK + d) =
                    make_float2(v0, v1);
                *(float2*)(C + (((size_t)(b1i * HH + h)) * SS + s1i) * DK + d) =
                    make_float2(v2, v3);
            }
        }
    }
}

// ============================================================================
// fp16x3 split GEMM body (V projection): 22-bit accurate.
// ============================================================================
__device__ void hgemm3_body(const float* __restrict__ Ag,
                            const float* __restrict__ Bg,
                            float* __restrict__ Cg,
                            const float* __restrict__ bias,
                            int m0, int n0, char* smem_raw)
{
    typedef __half (*HArr)[40];
    HArr Ah = (HArr)(smem_raw);
    HArr Al = (HArr)(smem_raw + 10240);
    HArr Bh = (HArr)(smem_raw + 20480);
    HArr Bl = (HArr)(smem_raw + 30720);

    const int tid  = threadIdx.x;
    const int wid  = tid >> 5;
    const int lane = tid & 31;
    const int wm   = wid & 1;
    const int wn   = wid >> 1;
    const int qid  = lane >> 2;
    const int rid  = lane & 3;

    float acc[4][4][4];
#pragma unroll
    for (int i = 0; i < 4; i++)
#pragma unroll
        for (int j = 0; j < 4; j++)
#pragma unroll
            for (int t = 0; t < 4; t++) acc[i][j][t] = 0.f;

    for (int c = 0; c < DD / 32; c++) {
        const int k0 = c << 5;
        float4 va[4], vb[4];
#pragma unroll
        for (int i = 0; i < 4; i++) {
            int idx = tid + i * 256;
            int r = idx >> 3, cc = (idx & 7) << 2;
            va[i] = *(const float4*)(Ag + (size_t)(m0 + r) * DD + k0 + cc);
            vb[i] = *(const float4*)(Bg + (size_t)(n0 + r) * DD + k0 + cc);
        }
        __syncthreads();
#pragma unroll
        for (int i = 0; i < 4; i++) {
            int idx = tid + i * 256;
            int r = idx >> 3, cc = (idx & 7) << 2;
            float xa[4] = {va[i].x, va[i].y, va[i].z, va[i].w};
            float xb[4] = {vb[i].x, vb[i].y, vb[i].z, vb[i].w};
#pragma unroll
            for (int t = 0; t < 4; t++) {
                __half h = __float2half_rn(xa[t]);
                Ah[r][cc + t] = h;
                Al[r][cc + t] = __float2half_rn(xa[t] - __half2float(h));
                __half g = __float2half_rn(xb[t]);
                Bh[r][cc + t] = g;
                Bl[r][cc + t] = __float2half_rn(xb[t] - __half2float(g));
            }
        }
        __syncthreads();

#pragma unroll
        for (int kk = 0; kk < 32; kk += 16) {
            u32 ah[4][4], al[4][4], bh[4][2], bl[4][2];
#pragma unroll
            for (int mt = 0; mt < 4; mt++) {
                int row = wm * 64 + mt * 16 + qid;
                ah[mt][0] = *(const u32*)&Ah[row    ][kk + rid * 2];
                ah[mt][1] = *(const u32*)&Ah[row + 8][kk + rid * 2];
                ah[mt][2] = *(const u32*)&Ah[row    ][kk + rid * 2 + 8];
                ah[mt][3] = *(const u32*)&Ah[row + 8][kk + rid * 2 + 8];
                al[mt][0] = *(const u32*)&Al[row    ][kk + rid * 2];
                al[mt][1] = *(const u32*)&Al[row + 8][kk + rid * 2];
                al[mt][2] = *(const u32*)&Al[row    ][kk + rid * 2 + 8];
                al[mt][3] = *(const u32*)&Al[row + 8][kk + rid * 2 + 8];
            }
#pragma unroll
            for (int nt = 0; nt < 4; nt++) {
                int col = wn * 32 + nt * 8 + qid;
                bh[nt][0] = *(const u32*)&Bh[col][kk + rid * 2];
                bh[nt][1] = *(const u32*)&Bh[col][kk + rid * 2 + 8];
                bl[nt][0] = *(const u32*)&Bl[col][kk + rid * 2];
                bl[nt][1] = *(const u32*)&Bl[col][kk + rid * 2 + 8];
            }
#pragma unroll
            for (int mt = 0; mt < 4; mt++)
#pragma unroll
                for (int nt = 0; nt < 4; nt++) {
                    mma_f16(acc[mt][nt], ah[mt], bh[nt]);
                    mma_f16(acc[mt][nt], ah[mt], bl[nt]);
                    mma_f16(acc[mt][nt], al[mt], bh[nt]);
                }
        }
        __syncthreads();
    }

#pragma unroll
    for (int mt = 0; mt < 4; mt++) {
        int r0 = m0 + wm * 64 + mt * 16 + qid;
        int r1 = r0 + 8;
#pragma unroll
        for (int nt = 0; nt < 4; nt++) {
            int cb = n0 + wn * 32 + nt * 8 + rid * 2;
            float b0 = bias[cb], b1 = bias[cb + 1];
            float v0 = acc[mt][nt][0] + b0;
            float v1 = acc[mt][nt][1] + b1;
            float v2 = acc[mt][nt][2] + b0;
            float v3 = acc[mt][nt][3] + b1;
            int h = cb >> 6, d = cb & 63;
            int b0i = r0 >> 11, s0i = r0 & (SS - 1);
            int b1i = r1 >> 11, s1i = r1 & (SS - 1);
            *(float2*)(Cg + (((size_t)(b0i * HH + h)) * SS + s0i) * DK + d) =
                make_float2(v0, v1);
            *(float2*)(Cg + (((size_t)(b1i * HH + h)) * SS + s1i) * DK + d) =
                make_float2(v2, v3);
        }
    }
}

// ============================================================================
// QK projections, pipe-mixed with x%3 interleave (R13 layout).
// ============================================================================
__global__ __launch_bounds__(256, 2)
void qk_mixed(const float* __restrict__ q,  const float* __restrict__ Wq,
              const float* __restrict__ bq, float* __restrict__ qh,
              const float* __restrict__ k,  const float* __restrict__ Wk,
              const float* __restrict__ bk, float* __restrict__ kh)
{
    __shared__ __align__(16) char smem_raw[46080];
    const float* A  = blockIdx.z ? k  : q;
    const float* B  = blockIdx.z ? Wk : Wq;
    const float* bi = blockIdx.z ? bk : bq;
    float*       C  = blockIdx.z ? kh : qh;
    const int m0 = blockIdx.y * 128;
    const int x = blockIdx.x;

    if (x % 3 == 0) {
        float (*As)[8][128] = (float(*)[8][128])(smem_raw);
        float (*Bs)[8][128] = (float(*)[8][128])(smem_raw + 8192);
        ffma_tile<1>(A, B, C, bi, DD, DD, DD, 0, 1.f,
                     m0, (x / 3) * 128, As, Bs);
    } else {
        int hi = 2 * (x / 3) + (x % 3) - 1;   // 0..7
        f16x6_tile<1>(A, B, C, bi, DD, DD, DD, 0, 1.f,
                      m0, 512 + hi * 64, smem_raw);
    }
}

// ============================================================================
// Scores, pipe-mixed (x%3 interleave) + V projection (z==32). (R13 layout)
// ============================================================================
__global__ __launch_bounds__(256, 2)
void scores_vproj_mixed(const float* __restrict__ qh, const float* __restrict__ kh,
                        float* __restrict__ probs,
                        const float* __restrict__ v, const float* __restrict__ Wv,
                        const float* __restrict__ bv, float* __restrict__ vh)
{
    __shared__ __align__(16) char smem_raw[46080];

    if (blockIdx.z < 32) {
        const size_t z = blockIdx.z;
        const float* A = qh + z * SS * DK;
        const float* B = kh + z * SS * DK;
        float* C = probs + z * SS * SS;
        const int m0 = blockIdx.y * 128;
        const int x = blockIdx.x;
        if (x % 3 == 0) {
            float (*As)[8][128] = (float(*)[8][128])(smem_raw);
            float (*Bs)[8][128] = (float(*)[8][128])(smem_raw + 8192);
            ffma_tile<0>(A, B, C, nullptr, DK, DK, DK, SS, 0.125f,
                         m0, (x / 3) * 128, As, Bs);
        } else {
            int hi = 2 * (x / 3) + (x % 3) - 1;   // 0..15
            f16x6_tile<0>(A, B, C, nullptr, DK, DK, DK, SS, 0.125f,
                          m0, 1024 + hi * 64, smem_raw);
        }
    } else {
        int flat = blockIdx.y * 24 + blockIdx.x;   // 0..383
        if (flat >= 256) return;
        int m0 = (flat >> 3) * 128;
        int n0 = (flat & 7) * 128;
        hgemm3_body(v, Wv, vh, bv, m0, n0, smem_raw);
    }
}

// ============================================================================
// AV with in-kernel mask + V transpose (replaces vt_mask + old AV):
// out[q][d] = sum_s (P16[q][s] * mask[s]) * fp16(V[s][d]).
// Bitwise-equal to masked-V variant since mask in {0,1} is exact in fp16.
// CTA 128(m) x 64(n=DK), BK=32, 8 warps 2(m)x4(n), NFR=2.
// ============================================================================
__global__ __launch_bounds__(256)
void av_masked(const __half* __restrict__ probsh, const float* __restrict__ vh,
               const float* __restrict__ maskg, __half* __restrict__ concath)
{
    __shared__ __half As[128][40];
    __shared__ __half Bs[64][40];
    __shared__ __half msk[SS];

    const int bh = blockIdx.z;
    const int b = bh >> 4, h = bh & 15;
    const int m0 = blockIdx.y * 128;
    const int tid  = threadIdx.x;
    const int wid  = tid >> 5;
    const int lane = tid & 31;
    const int wm   = wid & 1;
    const int wn   = wid >> 1;
    const int qid  = lane >> 2;
    const int rid  = lane & 3;

    for (int j = tid; j < SS; j += 256)
        msk[j] = __float2half_rn(maskg[bh * SS + j]);
    __syncthreads();

    const __half* A = probsh + (size_t)bh * SS * SS;
    const float*  V = vh     + (size_t)bh * SS * DK;

    float acc[4][2][4];
#pragma unroll
    for (int i = 0; i < 4; i++)
#pragma unroll
        for (int j = 0; j < 2; j++)
#pragma unroll
            for (int t = 0; t < 4; t++) acc[i][j][t] = 0.f;

    for (int c = 0; c < SS / 32; c++) {
        const int k0 = c << 5;
        uint4 va[2];
        float4 vb[2];
#pragma unroll
        for (int i = 0; i < 2; i++) {
            int idx = tid + i * 256;               // A: 128x32 h = 512 uint4
            int r = idx >> 2, seg = (idx & 3) << 3;
            va[i] = *(const uint4*)(A + (size_t)(m0 + r) * SS + k0 + seg);
        }
#pragma unroll
        for (int i = 0; i < 2; i++) {
            int idx = tid + i * 256;               // V: 32x64 f32 = 512 float4
            int r = idx >> 4, cc = (idx & 15) << 2;
            vb[i] = *(const float4*)(V + (size_t)(k0 + r) * DK + cc);
        }
        __syncthreads();
        // store A masked (mask exact in fp16: 0/1)
#pragma unroll
        for (int i = 0; i < 2; i++) {
            int idx = tid + i * 256;
            int r = idx >> 2, seg = (idx & 3) << 3;
            const __half2* mp = (const __half2*)&msk[k0 + seg];
            __half2 hx[4];
            *(uint4*)hx = va[i];
#pragma unroll
            for (int t = 0; t < 4; t++) hx[t] = __hmul2(hx[t], mp[t]);
            *(uint4*)&As[r][seg] = *(uint4*)hx;
        }
        // store B transposed: Bs[d][s_local] = fp16(V[k0+s][d])
#pragma unroll
        for (int i = 0; i < 2; i++) {
            int idx = tid + i * 256;
            int r = idx >> 4, cc = (idx & 15) << 2;
            Bs[cc + 0][r] = __float2half_rn(vb[i].x);
            Bs[cc + 1][r] = __float2half_rn(vb[i].y);
            Bs[cc + 2][r] = __float2half_rn(vb[i].z);
            Bs[cc + 3][r] = __float2half_rn(vb[i].w);
        }
        __syncthreads();

#pragma unroll
        for (int kk = 0; kk < 32; kk += 16) {
            u32 af[4][4], bf[2][2];
#pragma unroll
            for (int mt = 0; mt < 4; mt++) {
                int row = wm * 64 + mt * 16 + qid;
                af[mt][0] = *(const u32*)&As[row    ][kk + rid * 2];
                af[mt][1] = *(const u32*)&As[row + 8][kk + rid * 2];
                af[mt][2] = *(const u32*)&As[row    ][kk + rid * 2 + 8];
                af[mt][3] = *(const u32*)&As[row + 8][kk + rid * 2 + 8];
            }
#pragma unroll
            for (int nt = 0; nt < 2; nt++) {
                int col = wn * 16 + nt * 8 + qid;
                bf[nt][0] = *(const u32*)&Bs[col][kk + rid * 2];
                bf[nt][1] = *(const u32*)&Bs[col][kk + rid * 2 + 8];
            }
#pragma unroll
            for (int mt = 0; mt < 4; mt++)
#pragma unroll
                for (int nt = 0; nt < 2; nt++)
                    mma_f16(acc[mt][nt], af[mt], bf[nt]);
        }
        __syncthreads();
    }

#pragma unroll
    for (int mt = 0; mt < 4; mt++) {
        int r0 = m0 + wm * 64 + mt * 16 + qid;
        int r1 = r0 + 8;
#pragma unroll
        for (int nt = 0; nt < 2; nt++) {
            int cb = wn * 16 + nt * 8 + rid * 2;
            *(__half2*)(concath + ((size_t)b * SS + r0) * DD + h * DK + cb) =
                __floats2half2_rn(acc[mt][nt][0], acc[mt][nt][1]);
            *(__half2*)(concath + ((size_t)b * SS + r1) * DD + h * DK + cb) =
                __floats2half2_rn(acc[mt][nt][2], acc[mt][nt][3]);
        }
    }
}

// ============================================================================
// fp16 m16n8k16 NT GEMM, R13 form (O projection: A fp16, B fp32->cvt).
// ============================================================================
__global__ __launch_bounds__(256)
void hgemm_oproj(const __half* __restrict__ Ag, const float* __restrict__ Bg,
                 float* __restrict__ Cf, const float* __restrict__ bias)
{
    __shared__ __half As[128][56];
    __shared__ __half Bs[128][56];

    const int tid  = threadIdx.x;
    const int wid  = tid >> 5;
    const int lane = tid & 31;
    const int wm   = wid & 1;
    const int wn   = wid >> 1;
    const int qid  = lane >> 2;
    const int rid  = lane & 3;

    const int m0 = blockIdx.y * 128;
    const int n0 = blockIdx.x * 128;

    float acc[4][4][4];
#pragma unroll
    for (int i = 0; i < 4; i++)
#pragma unroll
        for (int j = 0; j < 4; j++)
#pragma unroll
            for (int t = 0; t < 4; t++) acc[i][j][t] = 0.f;

    for (int c = 0; c < DD / 32; c++) {
        const int k0 = c << 5;
        uint4 va[2];
#pragma unroll
        for (int i = 0; i < 2; i++) {
            int idx = tid + i * 256;
            int r = idx >> 2, seg = (idx & 3) << 3;
            va[i] = *(const uint4*)(Ag + (size_t)(m0 + r) * DD + k0 + seg);
        }
        float4 vb[4];
#pragma unroll
        for (int i = 0; i < 4; i++) {
            int idx = tid + i * 256;
            int r = idx >> 3, seg = (idx & 7) << 2;
            vb[i] = *(const float4*)(Bg + (size_t)(n0 + r) * DD + k0 + seg);
        }
        __syncthreads();
#pragma unroll
        for (int i = 0; i < 2; i++) {
            int idx = tid + i * 256;
            int r = idx >> 2, seg = (idx & 3) << 3;
            *(uint4*)&As[r][seg] = va[i];
        }
#pragma unroll
        for (int i = 0; i < 4; i++) {
            int idx = tid + i * 256;
            int r = idx >> 3, seg = (idx & 7) << 2;
            *(__half2*)&Bs[r][seg]     = __floats2half2_rn(vb[i].x, vb[i].y);
            *(__half2*)&Bs[r][seg + 2] = __floats2half2_rn(vb[i].z, vb[i].w);
        }
        __syncthreads();

#pragma unroll
        for (int kk = 0; kk < 32; kk += 16) {
            u32 af[4][4], bf[4][2];
#pragma unroll
            for (int mt = 0; mt < 4; mt++) {
                int row = wm * 64 + mt * 16 + qid;
                af[mt][0] = *(const u32*)&As[row    ][kk + rid * 2];
                af[mt][1] = *(const u32*)&As[row + 8][kk + rid * 2];
                af[mt][2] = *(const u32*)&As[row    ][kk + rid * 2 + 8];
                af[mt][3] = *(const u32*)&As[row + 8][kk + rid * 2 + 8];
            }
#pragma unroll
            for (int nt = 0; nt < 4; nt++) {
                int col = wn * 32 + nt * 8 + qid;
                bf[nt][0] = *(const u32*)&Bs[col][kk + rid * 2];
                bf[nt][1] = *(const u32*)&Bs[col][kk + rid * 2 + 8];
            }
#pragma unroll
            for (int mt = 0; mt < 4; mt++)
#pragma unroll
                for (int nt = 0; nt < 4; nt++)
                    mma_f16(acc[mt][nt], af[mt], bf[nt]);
        }
        __syncthreads();
    }

#pragma unroll
    for (int mt = 0; mt < 4; mt++) {
        int r0 = m0 + wm * 64 + mt * 16 + qid;
        int r1 = r0 + 8;
#pragma unroll
        for (int nt = 0; nt < 4; nt++) {
            int cb = n0 + wn * 32 + nt * 8 + rid * 2;
            float b0 = bias[cb], b1 = bias[cb + 1];
            *(float2*)(Cf + (size_t)r0 * DD + cb) =
                make_float2(acc[mt][nt][0] + b0, acc[mt][nt][1] + b1);
            *(float2*)(Cf + (size_t)r1 * DD + cb) =
                make_float2(acc[mt][nt][2] + b0, acc[mt][nt][3] + b1);
        }
    }
}

// ============================================================================
// Fused softmax + colsum partials; fp16 probs out. FOUR rows per iteration
// (ILP); per-row reduction sequence & cs order bitwise identical to R13.
// ============================================================================
__global__ __launch_bounds__(256)
void softmax_colsum_kernel(const float* __restrict__ scores,
                           __half* __restrict__ probsh,
                           float* __restrict__ part)
{
    __shared__ float redA[4][8];
    __shared__ float redB[4][8];
    const int rb = blockIdx.x;   // 0..31
    const int bh = blockIdx.y;
    const int tid = threadIdx.x;
    const int wid = tid >> 5, lane = tid & 31;

    float cs[8];
#pragma unroll
    for (int i = 0; i < 8; i++) cs[i] = 0.f;

    for (int r = 0; r < 64; r += 4) {
        float x[4][8];
        const float* rowp = scores + ((size_t)bh * SS + rb * 64 + r) * SS + tid * 8;
#pragma unroll
        for (int u = 0; u < 4; u++) {
            *(float4*)(x[u])     = *(const float4*)(rowp + (size_t)u * SS);
            *(float4*)(x[u] + 4) = *(const float4*)(rowp + (size_t)u * SS + 4);
        }

        float m[4];
#pragma unroll
        for (int u = 0; u < 4; u++) {
            m[u] = x[u][0];
#pragma unroll
            for (int i = 1; i < 8; i++) m[u] = fmaxf(m[u], x[u][i]);
        }
#pragma unroll
        for (int o = 16; o > 0; o >>= 1)
#pragma unroll
            for (int u = 0; u < 4; u++)
                m[u] = fmaxf(m[u], __shfl_xor_sync(0xFFFFFFFF, m[u], o));
        if (lane == 0) {
#pragma unroll
            for (int u = 0; u < 4; u++) redA[u][wid] = m[u];
        }
        __syncthreads();
#pragma unroll
        for (int u = 0; u < 4; u++) {
            m[u] = redA[u][0];
#pragma unroll
            for (int w = 1; w < 8; w++) m[u] = fmaxf(m[u], redA[u][w]);
        }

        float s[4] = {0.f, 0.f, 0.f, 0.f};
#pragma unroll
        for (int u = 0; u < 4; u++)
#pragma unroll
            for (int i = 0; i < 8; i++) {
                x[u][i] = __expf(x[u][i] - m[u]);
                s[u] += x[u][i];
            }
#pragma unroll
        for (int o = 16; o > 0; o >>= 1)
#pragma unroll
            for (int u = 0; u < 4; u++)
                s[u] += __shfl_xor_sync(0xFFFFFFFF, s[u], o);
        if (lane == 0) {
#pragma unroll
            for (int u = 0; u < 4; u++) redB[u][wid] = s[u];
        }
        __syncthreads();
#pragma unroll
        for (int u = 0; u < 4; u++) {
            s[u] = redB[u][0];
#pragma unroll
            for (int w = 1; w < 8; w++) s[u] += redB[u][w];
        }

#pragma unroll
        for (int u = 0; u < 4; u++) {
            float inv = 1.0f / s[u];
            __half2 hh[4];
#pragma unroll
            for (int i = 0; i < 8; i += 2) {
                float p0 = x[u][i] * inv, p1 = x[u][i + 1] * inv;
                cs[i] += p0; cs[i + 1] += p1;
                hh[i >> 1] = __floats2half2_rn(p0, p1);
            }
            *(uint4*)(probsh + ((size_t)bh * SS + rb * 64 + r + u) * SS + tid * 8) =
                *(uint4*)hh;
        }
        __syncthreads();
    }
#pragma unroll
    for (int i = 0; i < 8; i++)
        part[((size_t)bh * 32 + rb) * SS + tid * 8 + i] = cs[i];
}

// ============================================================================
// Fused colsum-reduce + top-k mask (bitonic sort). One block per (b,h).
// ============================================================================
__global__ void topk_mask_kernel(const float* __restrict__ part,
                                 float* __restrict__ mask)
{
    __shared__ float s[SS];
    __shared__ float cs_sh[SS];
    const int bh = blockIdx.x;
    const int tid = threadIdx.x;

    for (int j = tid; j < SS; j += 1024) {
        float sum = 0.f;
#pragma unroll
        for (int rb = 0; rb < 32; rb++)
            sum += part[((size_t)bh * 32 + rb) * SS + j];
        s[j] = sum;
        cs_sh[j] = sum;
    }
    __syncthreads();

    for (int ksz = 2; ksz <= SS; ksz <<= 1) {
        for (int j = ksz >> 1; j > 0; j >>= 1) {
            for (int i = tid; i < SS; i += 1024) {
                int p = i ^ j;
                if (p > i) {
                    bool up = ((i & ksz) == 0);
                    float a = s[i], b = s[p];
                    if ((a > b) == up) { s[i] = b; s[p] = a; }
                }
            }
            __syncthreads();
        }
    }
    float thr = s[SS - KEEP];
    mask[bh * SS + tid]        = (cs_sh[tid]        >= thr) ? 1.f : 0.f;
    mask[bh * SS + tid + 1024] = (cs_sh[tid + 1024] >= thr) ? 1.f : 0.f;
}

// ---------------------------------------------------------------------------
extern "C" void kernel_launch(void* const* d_in, const int* in_sizes, int n_in,
                              void* d_out, int out_size)
{
    (void)in_sizes; (void)n_in; (void)out_size;
    const float* q  = (const float*)d_in[0];
    const float* k  = (const float*)d_in[1];
    const float* v  = (const float*)d_in[2];
    const float* Wq = (const float*)d_in[3];
    const float* bq = (const float*)d_in[4];
    const float* Wk = (const float*)d_in[5];
    const float* bk = (const float*)d_in[6];
    const float* Wv = (const float*)d_in[7];
    const float* bv = (const float*)d_in[8];
    const float* Wo = (const float*)d_in[9];
    const float* bo = (const float*)d_in[10];
    float* out = (float*)d_out;

    float *qh, *kh, *vh, *probs, *part, *mask;
    __half *probsh, *concath;
    cudaGetSymbolAddress((void**)&qh,      g_qh);
    cudaGetSymbolAddress((void**)&kh,      g_kh);
    cudaGetSymbolAddress((void**)&vh,      g_vh);
    cudaGetSymbolAddress((void**)&probs,   g_probs);
    cudaGetSymbolAddress((void**)&probsh,  g_probsh);
    cudaGetSymbolAddress((void**)&part,    g_part);
    cudaGetSymbolAddress((void**)&mask,    g_mask);
    cudaGetSymbolAddress((void**)&concath, g_concath);

    // Q + K projections, FFMA/HMMA pipe-mixed (x%3 interleave)
    dim3 gqk(12, (BB * SS) / 128, 2);
    qk_mixed<<<gqk, 256>>>(q, Wq, bq, qh, k, Wk, bk, kh);

    // Scores (pipe-mixed, x%3 interleave) + V projection (z==32)
    dim3 gsv(24, SS / 128, BHN + 1);
    scores_vproj_mixed<<<gsv, 256>>>(qh, kh, probs, v, Wv, bv, vh);

    // Fused softmax + colsum partials (fp16 probs out), 4-row ILP
    softmax_colsum_kernel<<<dim3(32, BHN), 256>>>(probs, probsh, part);

    // Fused colsum reduce + top-k mask
    topk_mask_kernel<<<BHN, 1024>>>(part, mask);

    // AV with in-kernel mask + V transpose -> fp16 concat
    dim3 gav(1, SS / 128, BHN);
    av_masked<<<gav, 256>>>(probsh, vh, mask, concath);

    // Output projection (fp16 mma): fp32 out + bias
    dim3 gop(DD / 128, (BB * SS) / 128, 1);
    hgemm_oproj<<<gop, 256>>>(concath, Wo, out, bo);
}